// round 5
// baseline (speedup 1.0000x reference)
#include <cuda_runtime.h>
#include <math_constants.h>
#include <cstdint>

#define N_PRED 8192
#define M_GT   32768
#define BLK    256
#define QPT    4          // queries per thread in minval
#define NSEG_A 16         // segments over M (pass A), segLen 2048
#define NSEG_B 16         // segments over N (pass B), segLen 512
#define SEGLEN_A (M_GT / NSEG_A)
#define SEGLEN_B (N_PRED / NSEG_B)
#define RS_A   8          // rescan split pass A: chunk 256
#define RS_B   2          // rescan split pass B: chunk 256
#define NGATHER_BLOCKS ((N_PRED + M_GT) / BLK)   // 160

typedef unsigned long long ull;

// ── scratch (no allocations allowed) ────────────────────────────────────────
__device__ __align__(16) float g_soaP[4 * N_PRED];  // x | y | z | x^2+y^2+z^2
__device__ __align__(16) float g_soaG[4 * M_GT];
__device__ float g_segA[N_PRED * NSEG_A];
__device__ float g_segB[M_GT * NSEG_B];
__device__ int   g_idxA[N_PRED];
__device__ int   g_idxB[M_GT];
__device__ float g_part[NGATHER_BLOCKS];

// ── packed f32x2 helpers ────────────────────────────────────────────────────
__device__ __forceinline__ ull bcast2(float v) {
    ull r; asm("mov.b64 %0, {%1, %1};" : "=l"(r) : "f"(v)); return r;
}
__device__ __forceinline__ ull fma2(ull a, ull b, ull c) {
    ull d; asm("fma.rn.f32x2 %0, %1, %2, %3;" : "=l"(d) : "l"(a), "l"(b), "l"(c));
    return d;
}
__device__ __forceinline__ void min2(float& lo, float& hi, ull a) {
    float x, y;
    asm("mov.b64 {%0, %1}, %2;" : "=f"(x), "=f"(y) : "l"(a));
    lo = fminf(lo, x); hi = fminf(hi, y);
}
#define LD2(a, b, p) \
    asm("ld.global.nc.v2.b64 {%0, %1}, [%2];" : "=l"(a), "=l"(b) : "l"(p))

// ── prep: SoA transpose + |r|^2 + idx init ──────────────────────────────────
__global__ void prep_kernel(const float* __restrict__ pred,
                            const float* __restrict__ gt) {
    const int i = blockIdx.x * BLK + threadIdx.x;   // grid covers M_GT
    if (i < N_PRED) {
        const float x = pred[3 * i], y = pred[3 * i + 1], z = pred[3 * i + 2];
        g_soaP[i]              = x;
        g_soaP[i + N_PRED]     = y;
        g_soaP[i + 2 * N_PRED] = z;
        g_soaP[i + 3 * N_PRED] = fmaf(x, x, fmaf(y, y, z * z));
        g_idxA[i] = 0x7FFFFFFF;
    }
    {
        const float x = gt[3 * i], y = gt[3 * i + 1], z = gt[3 * i + 2];
        g_soaG[i]            = x;
        g_soaG[i + M_GT]     = y;
        g_soaG[i + 2 * M_GT] = z;
        g_soaG[i + 3 * M_GT] = fmaf(x, x, fmaf(y, y, z * z));
        g_idxB[i] = 0x7FFFFFFF;
    }
}

// ── min-value pass: per (query, segment) min of d' = |r|^2 - 2 q·r ──────────
// (q-constant |q|^2 dropped: argmin-invariant.) Packed f32x2 math, 2 refs per
// FMA chain, 4 queries per thread. No index tracking in the hot loop.
__global__ void minval_kernel(const float* __restrict__ Qsoa, int qStride,
                              const float* __restrict__ Rsoa, int rStride,
                              int segLen, int nSeg,
                              float* __restrict__ segmin) {
    ull nx2[QPT], ny2[QPT], nz2[QPT];
    const int qBase = blockIdx.x * (BLK * QPT) + threadIdx.x;
    #pragma unroll
    for (int qq = 0; qq < QPT; ++qq) {
        const int q = qBase + qq * BLK;
        nx2[qq] = bcast2(-2.0f * Qsoa[q]);
        ny2[qq] = bcast2(-2.0f * Qsoa[q + qStride]);
        nz2[qq] = bcast2(-2.0f * Qsoa[q + 2 * qStride]);
    }
    float bl[QPT], bh[QPT];
    #pragma unroll
    for (int qq = 0; qq < QPT; ++qq) { bl[qq] = CUDART_INF_F; bh[qq] = CUDART_INF_F; }

    const float* px = Rsoa + blockIdx.y * segLen;
    const float* py = px + rStride;
    const float* pz = py + rStride;
    const float* pw = pz + rStride;

    for (int t = 0; t < segLen; t += 4) {
        ull x01, x23, y01, y23, z01, z23, w01, w23;
        LD2(x01, x23, px + t);
        LD2(y01, y23, py + t);
        LD2(z01, z23, pz + t);
        LD2(w01, w23, pw + t);
        #pragma unroll
        for (int qq = 0; qq < QPT; ++qq) {
            ull a = fma2(nz2[qq], z01, w01);
            a     = fma2(ny2[qq], y01, a);
            a     = fma2(nx2[qq], x01, a);
            min2(bl[qq], bh[qq], a);
            ull b = fma2(nz2[qq], z23, w23);
            b     = fma2(ny2[qq], y23, b);
            b     = fma2(nx2[qq], x23, b);
            min2(bl[qq], bh[qq], b);
        }
    }
    #pragma unroll
    for (int qq = 0; qq < QPT; ++qq) {
        const int q = qBase + qq * BLK;
        segmin[q * nSeg + blockIdx.y] = fminf(bl[qq], bh[qq]);
    }
}

// ── rescan: recover first-min index from the winning segment(s) ─────────────
// Bit-exact recompute (same fmaf nesting as the f32x2 lanes), equality match,
// atomicMin -> min matching j == jnp.argmin first-min semantics.
__global__ void rescan_kernel(const float* __restrict__ Qsoa, int qStride,
                              const float* __restrict__ Rsoa, int rStride,
                              const float* __restrict__ segmin, int nSeg,
                              int segLen, int chunk,
                              int* __restrict__ idxOut) {
    const int qi = blockIdx.x * BLK + threadIdx.x;
    const float nx = -2.0f * Qsoa[qi];
    const float ny = -2.0f * Qsoa[qi + qStride];
    const float nz = -2.0f * Qsoa[qi + 2 * qStride];

    const float* sm = segmin + qi * nSeg;
    float bd = sm[0];
    for (int s = 1; s < nSeg; ++s) bd = fminf(bd, sm[s]);

    int jf = 0x7FFFFFFF;
    for (int s = 0; s < nSeg; ++s) {
        if (sm[s] != bd) continue;
        const int base = s * segLen + blockIdx.y * chunk;
        for (int k = 0; k < chunk; k += 4) {
            #pragma unroll
            for (int u = 0; u < 4; ++u) {
                const int j = base + k + u;
                const float x = __ldg(Rsoa + j);
                const float y = __ldg(Rsoa + j + rStride);
                const float z = __ldg(Rsoa + j + 2 * rStride);
                const float w = __ldg(Rsoa + j + 3 * rStride);
                const float d = fmaf(nx, x, fmaf(ny, y, fmaf(nz, z, w)));
                if (d == bd) jf = min(jf, j);
            }
        }
    }
    if (jf != 0x7FFFFFFF) atomicMin(&idxOut[qi], jf);
}

// ── gather normals + deterministic block partial sums (both directions) ─────
__global__ void gather_kernel(const float* __restrict__ pn,
                              const float* __restrict__ gn) {
    const int i = blockIdx.x * BLK + threadIdx.x;   // 0 .. N+M-1
    float v;
    if (i < N_PRED) {
        const int j = min(g_idxA[i], M_GT - 1);
        v = (1.0f - (pn[3 * i] * gn[3 * j] + pn[3 * i + 1] * gn[3 * j + 1] +
                     pn[3 * i + 2] * gn[3 * j + 2])) * (1.0f / N_PRED);
    } else {
        const int q = i - N_PRED;
        const int j = min(g_idxB[q], N_PRED - 1);
        v = (1.0f - (gn[3 * q] * pn[3 * j] + gn[3 * q + 1] * pn[3 * j + 1] +
                     gn[3 * q + 2] * pn[3 * j + 2])) * (1.0f / M_GT);
    }
    #pragma unroll
    for (int off = 16; off > 0; off >>= 1) v += __shfl_xor_sync(0xFFFFFFFFu, v, off);
    __shared__ float sw[BLK / 32];
    if ((threadIdx.x & 31) == 0) sw[threadIdx.x >> 5] = v;
    __syncthreads();
    if (threadIdx.x == 0) {
        float s = 0.0f;
        #pragma unroll
        for (int w = 0; w < BLK / 32; ++w) s += sw[w];
        g_part[blockIdx.x] = s;
    }
}

__global__ void finalize_kernel(float* __restrict__ out) {
    if (threadIdx.x == 0) {
        float s = 0.0f;
        for (int i = 0; i < NGATHER_BLOCKS; ++i) s += g_part[i];
        out[0] = s;
    }
}

extern "C" void kernel_launch(void* const* d_in, const int* in_sizes, int n_in,
                              void* d_out, int out_size) {
    const float* pred_pts = (const float*)d_in[0];  // [1, 8192, 3]
    const float* pred_nrm = (const float*)d_in[1];  // [1, 8192, 3]
    const float* gt_pts   = (const float*)d_in[2];  // [1, 32768, 3]
    const float* gt_nrm   = (const float*)d_in[3];  // [1, 32768, 3]
    float* out = (float*)d_out;

    float *soaP, *soaG, *segA, *segB;
    int *idxA, *idxB;
    cudaGetSymbolAddress((void**)&soaP, g_soaP);
    cudaGetSymbolAddress((void**)&soaG, g_soaG);
    cudaGetSymbolAddress((void**)&segA, g_segA);
    cudaGetSymbolAddress((void**)&segB, g_segB);
    cudaGetSymbolAddress((void**)&idxA, g_idxA);
    cudaGetSymbolAddress((void**)&idxB, g_idxB);

    prep_kernel<<<M_GT / BLK, BLK>>>(pred_pts, gt_pts);

    // Pass A: pred -> gt (8192 queries over 32768 refs)
    minval_kernel<<<dim3(N_PRED / (BLK * QPT), NSEG_A), BLK>>>(
        soaP, N_PRED, soaG, M_GT, SEGLEN_A, NSEG_A, segA);
    // Pass B: gt -> pred (32768 queries over 8192 refs)
    minval_kernel<<<dim3(M_GT / (BLK * QPT), NSEG_B), BLK>>>(
        soaG, M_GT, soaP, N_PRED, SEGLEN_B, NSEG_B, segB);

    rescan_kernel<<<dim3(N_PRED / BLK, RS_A), BLK>>>(
        soaP, N_PRED, soaG, M_GT, segA, NSEG_A, SEGLEN_A, SEGLEN_A / RS_A, idxA);
    rescan_kernel<<<dim3(M_GT / BLK, RS_B), BLK>>>(
        soaG, M_GT, soaP, N_PRED, segB, NSEG_B, SEGLEN_B, SEGLEN_B / RS_B, idxB);

    gather_kernel<<<NGATHER_BLOCKS, BLK>>>(pred_nrm, gt_nrm);
    finalize_kernel<<<1, 32>>>(out);
}

// round 10
// speedup vs baseline: 4.9569x; 4.9569x over previous
#include <cuda_runtime.h>
#include <math_constants.h>
#include <cstdint>

#define N_PRED 8192
#define M_GT   32768
#define BLK    256
#define QPT    4          // queries per thread in minval
#define NSEG_A 32         // segments over M (pass A), segLen 1024
#define NSEG_B 16         // segments over N (pass B), segLen 512
#define SEGLEN_A (M_GT / NSEG_A)
#define SEGLEN_B (N_PRED / NSEG_B)
#define NGATHER_BLOCKS ((N_PRED + M_GT) / BLK)   // 160

typedef unsigned long long ull;

// ── scratch (no allocations allowed) ────────────────────────────────────────
__device__ __align__(16) float g_soaP[4 * N_PRED];  // x | y | z | x^2+y^2+z^2
__device__ __align__(16) float g_soaG[4 * M_GT];
__device__ float g_segA[N_PRED * NSEG_A];
__device__ float g_segB[M_GT * NSEG_B];
__device__ int   g_idxA[N_PRED];
__device__ int   g_idxB[M_GT];
__device__ float g_part[NGATHER_BLOCKS];

// ── packed f32x2 helpers ────────────────────────────────────────────────────
__device__ __forceinline__ ull bcast2(float v) {
    ull r; asm("mov.b64 %0, {%1, %1};" : "=l"(r) : "f"(v)); return r;
}
__device__ __forceinline__ ull fma2(ull a, ull b, ull c) {
    ull d; asm("fma.rn.f32x2 %0, %1, %2, %3;" : "=l"(d) : "l"(a), "l"(b), "l"(c));
    return d;
}
__device__ __forceinline__ void min2(float& lo, float& hi, ull a) {
    float x, y;
    asm("mov.b64 {%0, %1}, %2;" : "=f"(x), "=f"(y) : "l"(a));
    lo = fminf(lo, x); hi = fminf(hi, y);
}
#define LD2(a, b, p) \
    asm("ld.global.nc.v2.b64 {%0, %1}, [%2];" : "=l"(a), "=l"(b) : "l"(p))

// ── prep: SoA transpose + |r|^2 ─────────────────────────────────────────────
__global__ void prep_kernel(const float* __restrict__ pred,
                            const float* __restrict__ gt) {
    const int i = blockIdx.x * BLK + threadIdx.x;   // grid covers M_GT
    if (i < N_PRED) {
        const float x = pred[3 * i], y = pred[3 * i + 1], z = pred[3 * i + 2];
        g_soaP[i]              = x;
        g_soaP[i + N_PRED]     = y;
        g_soaP[i + 2 * N_PRED] = z;
        g_soaP[i + 3 * N_PRED] = fmaf(x, x, fmaf(y, y, z * z));
    }
    {
        const float x = gt[3 * i], y = gt[3 * i + 1], z = gt[3 * i + 2];
        g_soaG[i]            = x;
        g_soaG[i + M_GT]     = y;
        g_soaG[i + 2 * M_GT] = z;
        g_soaG[i + 3 * M_GT] = fmaf(x, x, fmaf(y, y, z * z));
    }
}

// ── min-value pass: per (query, segment) min of d' = |r|^2 - 2 q·r ──────────
// (q-constant |q|^2 dropped: argmin-invariant.) Packed f32x2 math, 2 refs per
// FMA chain, 4 queries per thread. No index tracking in the hot loop.
__global__ void minval_kernel(const float* __restrict__ Qsoa, int qStride,
                              const float* __restrict__ Rsoa, int rStride,
                              int segLen, int nSeg,
                              float* __restrict__ segmin) {
    ull nx2[QPT], ny2[QPT], nz2[QPT];
    const int qBase = blockIdx.x * (BLK * QPT) + threadIdx.x;
    #pragma unroll
    for (int qq = 0; qq < QPT; ++qq) {
        const int q = qBase + qq * BLK;
        nx2[qq] = bcast2(-2.0f * Qsoa[q]);
        ny2[qq] = bcast2(-2.0f * Qsoa[q + qStride]);
        nz2[qq] = bcast2(-2.0f * Qsoa[q + 2 * qStride]);
    }
    float bl[QPT], bh[QPT];
    #pragma unroll
    for (int qq = 0; qq < QPT; ++qq) { bl[qq] = CUDART_INF_F; bh[qq] = CUDART_INF_F; }

    const float* px = Rsoa + blockIdx.y * segLen;
    const float* py = px + rStride;
    const float* pz = py + rStride;
    const float* pw = pz + rStride;

    for (int t = 0; t < segLen; t += 4) {
        ull x01, x23, y01, y23, z01, z23, w01, w23;
        LD2(x01, x23, px + t);
        LD2(y01, y23, py + t);
        LD2(z01, z23, pz + t);
        LD2(w01, w23, pw + t);
        #pragma unroll
        for (int qq = 0; qq < QPT; ++qq) {
            ull a = fma2(nz2[qq], z01, w01);
            a     = fma2(ny2[qq], y01, a);
            a     = fma2(nx2[qq], x01, a);
            min2(bl[qq], bh[qq], a);
            ull b = fma2(nz2[qq], z23, w23);
            b     = fma2(ny2[qq], y23, b);
            b     = fma2(nx2[qq], x23, b);
            min2(bl[qq], bh[qq], b);
        }
    }
    #pragma unroll
    for (int qq = 0; qq < QPT; ++qq) {
        const int q = qBase + qq * BLK;
        segmin[q * nSeg + blockIdx.y] = fminf(bl[qq], bh[qq]);
    }
}

// ── rescan: one WARP per query, divergence-free, coalesced ──────────────────
// Lanes 0..nSeg-1 read the segment minima; warp-reduce the min and pick the
// FIRST winning segment (ballot+ffs -> uniform). Global first-min j must live
// in that segment (segments are ascending-j ranges). All 32 lanes then scan
// that one segment cooperatively (lane-adjacent loads) with a bit-exact
// scalar recompute of the f32x2 lane math, and warp-min-reduce the matching j.
__global__ void rescan_kernel(const float* __restrict__ Qsoa, int qStride,
                              const float* __restrict__ Rsoa, int rStride,
                              const float* __restrict__ segmin, int nSeg,
                              int segLen,
                              int* __restrict__ idxOut) {
    const int lane = threadIdx.x & 31;
    const int qi = (blockIdx.x * blockDim.x + threadIdx.x) >> 5;

    const float* sm = segmin + qi * nSeg;
    float v = (lane < nSeg) ? sm[lane] : CUDART_INF_F;
    float bd = v;
    #pragma unroll
    for (int off = 16; off > 0; off >>= 1)
        bd = fminf(bd, __shfl_xor_sync(0xFFFFFFFFu, bd, off));
    const unsigned winners = __ballot_sync(0xFFFFFFFFu, v == bd);
    const int sstar = __ffs(winners) - 1;      // uniform across warp

    const float nx = -2.0f * Qsoa[qi];
    const float ny = -2.0f * Qsoa[qi + qStride];
    const float nz = -2.0f * Qsoa[qi + 2 * qStride];

    const int base = sstar * segLen;
    int jf = 0x7FFFFFFF;
    for (int t = lane; t < segLen; t += 32) {
        const int j = base + t;
        const float x = __ldg(Rsoa + j);
        const float y = __ldg(Rsoa + j + rStride);
        const float z = __ldg(Rsoa + j + 2 * rStride);
        const float w = __ldg(Rsoa + j + 3 * rStride);
        const float d = fmaf(nx, x, fmaf(ny, y, fmaf(nz, z, w)));
        if (d == bd) jf = min(jf, j);
    }
    #pragma unroll
    for (int off = 16; off > 0; off >>= 1)
        jf = min(jf, __shfl_xor_sync(0xFFFFFFFFu, jf, off));
    if (lane == 0) idxOut[qi] = jf;
}

// ── gather normals + deterministic block partial sums (both directions) ─────
__global__ void gather_kernel(const float* __restrict__ pn,
                              const float* __restrict__ gn) {
    const int i = blockIdx.x * BLK + threadIdx.x;   // 0 .. N+M-1
    float v;
    if (i < N_PRED) {
        const int j = g_idxA[i];
        v = (1.0f - (pn[3 * i] * gn[3 * j] + pn[3 * i + 1] * gn[3 * j + 1] +
                     pn[3 * i + 2] * gn[3 * j + 2])) * (1.0f / N_PRED);
    } else {
        const int q = i - N_PRED;
        const int j = g_idxB[q];
        v = (1.0f - (gn[3 * q] * pn[3 * j] + gn[3 * q + 1] * pn[3 * j + 1] +
                     gn[3 * q + 2] * pn[3 * j + 2])) * (1.0f / M_GT);
    }
    #pragma unroll
    for (int off = 16; off > 0; off >>= 1) v += __shfl_xor_sync(0xFFFFFFFFu, v, off);
    __shared__ float sw[BLK / 32];
    if ((threadIdx.x & 31) == 0) sw[threadIdx.x >> 5] = v;
    __syncthreads();
    if (threadIdx.x == 0) {
        float s = 0.0f;
        #pragma unroll
        for (int w = 0; w < BLK / 32; ++w) s += sw[w];
        g_part[blockIdx.x] = s;
    }
}

__global__ void finalize_kernel(float* __restrict__ out) {
    if (threadIdx.x == 0) {
        float s = 0.0f;
        for (int i = 0; i < NGATHER_BLOCKS; ++i) s += g_part[i];
        out[0] = s;
    }
}

extern "C" void kernel_launch(void* const* d_in, const int* in_sizes, int n_in,
                              void* d_out, int out_size) {
    const float* pred_pts = (const float*)d_in[0];  // [1, 8192, 3]
    const float* pred_nrm = (const float*)d_in[1];  // [1, 8192, 3]
    const float* gt_pts   = (const float*)d_in[2];  // [1, 32768, 3]
    const float* gt_nrm   = (const float*)d_in[3];  // [1, 32768, 3]
    float* out = (float*)d_out;

    float *soaP, *soaG, *segA, *segB;
    int *idxA, *idxB;
    cudaGetSymbolAddress((void**)&soaP, g_soaP);
    cudaGetSymbolAddress((void**)&soaG, g_soaG);
    cudaGetSymbolAddress((void**)&segA, g_segA);
    cudaGetSymbolAddress((void**)&segB, g_segB);
    cudaGetSymbolAddress((void**)&idxA, g_idxA);
    cudaGetSymbolAddress((void**)&idxB, g_idxB);

    prep_kernel<<<M_GT / BLK, BLK>>>(pred_pts, gt_pts);

    // Pass A: pred -> gt (8192 queries over 32768 refs)
    minval_kernel<<<dim3(N_PRED / (BLK * QPT), NSEG_A), BLK>>>(
        soaP, N_PRED, soaG, M_GT, SEGLEN_A, NSEG_A, segA);
    // Pass B: gt -> pred (32768 queries over 8192 refs)
    minval_kernel<<<dim3(M_GT / (BLK * QPT), NSEG_B), BLK>>>(
        soaG, M_GT, soaP, N_PRED, SEGLEN_B, NSEG_B, segB);

    // Rescans: one warp per query (8 warps per 256-thread block).
    rescan_kernel<<<N_PRED / (BLK / 32), BLK>>>(
        soaP, N_PRED, soaG, M_GT, segA, NSEG_A, SEGLEN_A, idxA);
    rescan_kernel<<<M_GT / (BLK / 32), BLK>>>(
        soaG, M_GT, soaP, N_PRED, segB, NSEG_B, SEGLEN_B, idxB);

    gather_kernel<<<NGATHER_BLOCKS, BLK>>>(pred_nrm, gt_nrm);
    finalize_kernel<<<1, 32>>>(out);
}

// round 11
// speedup vs baseline: 6.5578x; 1.3230x over previous
#include <cuda_runtime.h>
#include <math_constants.h>
#include <cstdint>

#define N_PRED 8192
#define M_GT   32768
#define BLK    256
#define QPT    4            // queries per thread in minval
#define NSEG_A 128          // segments over M (pass A), segLen 256
#define NSEG_B 64           // segments over N (pass B), segLen 128
#define SEGLEN_A (M_GT / NSEG_A)     // 256
#define SEGLEN_B (N_PRED / NSEG_B)   // 128
#define MV_A_BLOCKS ((N_PRED / (BLK * QPT)) * NSEG_A)   // 8 * 128 = 1024
#define MV_B_BLOCKS ((M_GT  / (BLK * QPT)) * NSEG_B)    // 32 * 64 = 2048
#define RS_A_BLOCKS (N_PRED / 8)     // 1024  (8 warps = 8 queries per block)
#define RS_B_BLOCKS (M_GT / 8)       // 4096
#define NACC 128

typedef unsigned long long ull;

// ── scratch (no allocations allowed) ────────────────────────────────────────
__device__ __align__(16) float g_soaP[4 * N_PRED];  // x | y | z | |p|^2
__device__ __align__(16) float g_soaG[4 * M_GT];
__device__ float g_segA[N_PRED * NSEG_A];
__device__ float g_segB[M_GT * NSEG_B];
__device__ float g_acc[NACC];

// ── packed f32x2 helpers ────────────────────────────────────────────────────
__device__ __forceinline__ ull bcast2(float v) {
    ull r; asm("mov.b64 %0, {%1, %1};" : "=l"(r) : "f"(v)); return r;
}
__device__ __forceinline__ ull fma2(ull a, ull b, ull c) {
    ull d; asm("fma.rn.f32x2 %0, %1, %2, %3;" : "=l"(d) : "l"(a), "l"(b), "l"(c));
    return d;
}
__device__ __forceinline__ void min2(float& lo, float& hi, ull a) {
    float x, y;
    asm("mov.b64 {%0, %1}, %2;" : "=f"(x), "=f"(y) : "l"(a));
    lo = fminf(lo, x); hi = fminf(hi, y);
}
#define LD2(a, b, p) \
    asm("ld.global.nc.v2.b64 {%0, %1}, [%2];" : "=l"(a), "=l"(b) : "l"(p))

// ── prep: SoA transpose + |r|^2 + accumulator zero ──────────────────────────
__global__ void prep_kernel(const float* __restrict__ pred,
                            const float* __restrict__ gt) {
    const int i = blockIdx.x * BLK + threadIdx.x;   // grid covers M_GT
    if (i < N_PRED) {
        const float x = pred[3 * i], y = pred[3 * i + 1], z = pred[3 * i + 2];
        g_soaP[i]              = x;
        g_soaP[i + N_PRED]     = y;
        g_soaP[i + 2 * N_PRED] = z;
        g_soaP[i + 3 * N_PRED] = fmaf(x, x, fmaf(y, y, z * z));
    }
    if (i < NACC) g_acc[i] = 0.0f;
    {
        const float x = gt[3 * i], y = gt[3 * i + 1], z = gt[3 * i + 2];
        g_soaG[i]            = x;
        g_soaG[i + M_GT]     = y;
        g_soaG[i + 2 * M_GT] = z;
        g_soaG[i + 3 * M_GT] = fmaf(x, x, fmaf(y, y, z * z));
    }
}

// ── min-value pass: per (query, segment) min of d' = |r|^2 - 2 q·r ──────────
// Packed f32x2 math, 2 refs per FMA chain, 4 queries per thread; no index
// tracking in the hot loop. q-constant |q|^2 dropped (argmin-invariant).
template <int QS, int RS, int SEGLEN, int NSEG>
__device__ __forceinline__ void minval_body(const float* __restrict__ Q,
                                            const float* __restrict__ R,
                                            float* __restrict__ segmin,
                                            int qblk, int seg) {
    ull nx2[QPT], ny2[QPT], nz2[QPT];
    const int qBase = qblk * (BLK * QPT) + threadIdx.x;
    #pragma unroll
    for (int qq = 0; qq < QPT; ++qq) {
        const int q = qBase + qq * BLK;
        nx2[qq] = bcast2(-2.0f * Q[q]);
        ny2[qq] = bcast2(-2.0f * Q[q + QS]);
        nz2[qq] = bcast2(-2.0f * Q[q + 2 * QS]);
    }
    float bl[QPT], bh[QPT];
    #pragma unroll
    for (int qq = 0; qq < QPT; ++qq) { bl[qq] = CUDART_INF_F; bh[qq] = CUDART_INF_F; }

    const float* px = R + seg * SEGLEN;
    const float* py = px + RS;
    const float* pz = py + RS;
    const float* pw = pz + RS;

    #pragma unroll 2
    for (int t = 0; t < SEGLEN; t += 4) {
        ull x01, x23, y01, y23, z01, z23, w01, w23;
        LD2(x01, x23, px + t);
        LD2(y01, y23, py + t);
        LD2(z01, z23, pz + t);
        LD2(w01, w23, pw + t);
        #pragma unroll
        for (int qq = 0; qq < QPT; ++qq) {
            ull a = fma2(nz2[qq], z01, w01);
            a     = fma2(ny2[qq], y01, a);
            a     = fma2(nx2[qq], x01, a);
            min2(bl[qq], bh[qq], a);
            ull b = fma2(nz2[qq], z23, w23);
            b     = fma2(ny2[qq], y23, b);
            b     = fma2(nx2[qq], x23, b);
            min2(bl[qq], bh[qq], b);
        }
    }
    #pragma unroll
    for (int qq = 0; qq < QPT; ++qq) {
        const int q = qBase + qq * BLK;
        segmin[q * NSEG + seg] = fminf(bl[qq], bh[qq]);
    }
}

// Merged minval: blocks [0, MV_A_BLOCKS) = pass A (heavier), rest = pass B.
__global__ void __launch_bounds__(BLK) minval_kernel() {
    int bx = blockIdx.x;
    if (bx < MV_A_BLOCKS) {
        minval_body<N_PRED, M_GT, SEGLEN_A, NSEG_A>(g_soaP, g_soaG, g_segA,
                                                    bx & 7, bx >> 3);
    } else {
        bx -= MV_A_BLOCKS;
        minval_body<M_GT, N_PRED, SEGLEN_B, NSEG_B>(g_soaG, g_soaP, g_segB,
                                                    bx & 31, bx >> 5);
    }
}

// ── rescan + inline normal loss: one WARP per query ─────────────────────────
// Warp reads NSEG segment minima (NSEG/32 per lane), reduces global min bd,
// picks the FIRST winning segment via lowest-word-first ballot cascade
// (uniform). Global first-min j lives in that segment (ascending-j ranges).
// 32 lanes scan that segment with a bit-exact scalar recompute of the f32x2
// lane math; min matching j == jnp.argmin first-min semantics. All lanes then
// know jf; lane 0 gathers normals and returns the scaled loss contribution.
template <int QS, int RS, int SEGLEN, int NSEG>
__device__ __forceinline__ float rescan_body(const float* __restrict__ Qsoa,
                                             const float* __restrict__ Rsoa,
                                             const float* __restrict__ segmin,
                                             const float* __restrict__ qN,
                                             const float* __restrict__ rN,
                                             float scale, int qi, int lane) {
    constexpr int NW = NSEG / 32;
    const float* sm = segmin + qi * NSEG;
    float v[NW];
    float bd = CUDART_INF_F;
    #pragma unroll
    for (int k = 0; k < NW; ++k) {
        v[k] = sm[lane + 32 * k];
        bd = fminf(bd, v[k]);
    }
    #pragma unroll
    for (int off = 16; off > 0; off >>= 1)
        bd = fminf(bd, __shfl_xor_sync(0xFFFFFFFFu, bd, off));

    int sstar = -1;
    #pragma unroll
    for (int k = 0; k < NW; ++k) {
        const unsigned b = __ballot_sync(0xFFFFFFFFu, v[k] == bd);
        if (sstar < 0 && b) sstar = 32 * k + __ffs(b) - 1;   // uniform
    }

    const float nx = -2.0f * Qsoa[qi];
    const float ny = -2.0f * Qsoa[qi + QS];
    const float nz = -2.0f * Qsoa[qi + 2 * QS];

    const int base = sstar * SEGLEN;
    int jf = 0x7FFFFFFF;
    #pragma unroll
    for (int t = lane; t < SEGLEN; t += 32) {
        const int j = base + t;
        const float x = Rsoa[j];
        const float y = Rsoa[j + RS];
        const float z = Rsoa[j + 2 * RS];
        const float w = Rsoa[j + 3 * RS];
        const float d = fmaf(nx, x, fmaf(ny, y, fmaf(nz, z, w)));
        if (d == bd) jf = min(jf, j);
    }
    #pragma unroll
    for (int off = 16; off > 0; off >>= 1)
        jf = min(jf, __shfl_xor_sync(0xFFFFFFFFu, jf, off));

    float out = 0.0f;
    if (lane == 0) {
        out = (1.0f - (qN[3 * qi]     * rN[3 * jf] +
                       qN[3 * qi + 1] * rN[3 * jf + 1] +
                       qN[3 * qi + 2] * rN[3 * jf + 2])) * scale;
    }
    return out;
}

// Merged rescan: blocks [0, RS_A_BLOCKS) = pass A, rest = pass B.
// 8 warps (= 8 queries) per block; block-reduce + spread atomicAdd.
__global__ void __launch_bounds__(BLK) rescan_kernel(const float* __restrict__ pn,
                                                     const float* __restrict__ gn) {
    const int lane = threadIdx.x & 31;
    const int w = threadIdx.x >> 5;
    float val;
    if (blockIdx.x < RS_A_BLOCKS) {
        const int qi = blockIdx.x * 8 + w;
        val = rescan_body<N_PRED, M_GT, SEGLEN_A, NSEG_A>(
            g_soaP, g_soaG, g_segA, pn, gn, 1.0f / N_PRED, qi, lane);
    } else {
        const int qi = (blockIdx.x - RS_A_BLOCKS) * 8 + w;
        val = rescan_body<M_GT, N_PRED, SEGLEN_B, NSEG_B>(
            g_soaG, g_soaP, g_segB, gn, pn, 1.0f / M_GT, qi, lane);
    }
    __shared__ float sw[8];
    if (lane == 0) sw[w] = val;
    __syncthreads();
    if (threadIdx.x == 0) {
        float s = 0.0f;
        #pragma unroll
        for (int k = 0; k < 8; ++k) s += sw[k];
        atomicAdd(&g_acc[blockIdx.x & (NACC - 1)], s);
    }
}

__global__ void finalize_kernel(float* __restrict__ out) {
    const int lane = threadIdx.x;   // 32 threads
    float s = 0.0f;
    for (int k = lane; k < NACC; k += 32) s += g_acc[k];
    #pragma unroll
    for (int off = 16; off > 0; off >>= 1)
        s += __shfl_xor_sync(0xFFFFFFFFu, s, off);
    if (lane == 0) out[0] = s;
}

extern "C" void kernel_launch(void* const* d_in, const int* in_sizes, int n_in,
                              void* d_out, int out_size) {
    const float* pred_pts = (const float*)d_in[0];  // [1, 8192, 3]
    const float* pred_nrm = (const float*)d_in[1];  // [1, 8192, 3]
    const float* gt_pts   = (const float*)d_in[2];  // [1, 32768, 3]
    const float* gt_nrm   = (const float*)d_in[3];  // [1, 32768, 3]
    float* out = (float*)d_out;

    prep_kernel<<<M_GT / BLK, BLK>>>(pred_pts, gt_pts);
    minval_kernel<<<MV_A_BLOCKS + MV_B_BLOCKS, BLK>>>();
    rescan_kernel<<<RS_A_BLOCKS + RS_B_BLOCKS, BLK>>>(pred_nrm, gt_nrm);
    finalize_kernel<<<1, 32>>>(out);
}